// round 16
// baseline (speedup 1.0000x reference)
#include <cuda_runtime.h>
#include <math.h>

#define L    3136
#define HW   56
#define DM   96
#define DI   192
#define NS   16
#define KDIR 4
#define RR   6
#define NCH  64
#define CL   49

// ---------------- scratch (device globals; no allocation) ----------------
__device__ float g_xc[DI * L];           // conv input, channel-major [d][s]
__device__ float g_z[L * DI];            // gate, pixel-major [s][d]
__device__ float g_xconv[DI * L];        // conv output, channel-major [d][s]
__device__ float g_xt[DI * L];           // transposed
__device__ float g_dts[KDIR * RR * L];   // low-rank dt, scan order [k*6+r][l]
// B/C in CHUNK-INTERLEAVED scan order: index (i*64+c)*16+n where l = c*49+i
__device__ float g_Bs[KDIR * L * NS];
__device__ float g_Cs[KDIR * L * NS];
__device__ float g_y4[KDIR * DI * L];    // per-direction y at SPATIAL index

__device__ __forceinline__ float siluf(float x) { return x / (1.f + __expf(-x)); }
__device__ __forceinline__ float softplusf(float x) {
    return x > 20.f ? x : __logf(1.f + __expf(x));
}
__device__ __forceinline__ float ex2f(float x) {
    float r;
    asm("ex2.approx.f32 %0, %1;" : "=f"(r) : "f"(x));
    return r;
}
#define LOG2E 1.4426950408889634f

// ---------------- K1: in_proj GEMM (L x 96) @ (96 x 384), split xc/z ------
__global__ void k_inproj(const float* __restrict__ x, const float* __restrict__ w) {
    __shared__ __align__(16) float As[32 * 96];
    __shared__ __align__(16) float Bs[96 * 65];
    __shared__ float Csh[64 * 33];
    const int l0 = blockIdx.x * 32;
    const int o0 = blockIdx.y * 64;
    const int tid = threadIdx.x;

    // float4 staging
    {
        const float4* x4 = (const float4*)x;
        float4* As4 = (float4*)As;
        for (int e4 = tid; e4 < 32 * 24; e4 += 256)
            As4[e4] = x4[l0 * 24 + e4];
        for (int e4 = tid; e4 < 64 * 24; e4 += 256) {
            int o = e4 / 24, c4 = e4 % 24;
            float4 wv = *(const float4*)&w[(o0 + o) * 96 + c4 * 4];
            int c = c4 * 4;
            Bs[(c + 0) * 65 + o] = wv.x;
            Bs[(c + 1) * 65 + o] = wv.y;
            Bs[(c + 2) * 65 + o] = wv.z;
            Bs[(c + 3) * 65 + o] = wv.w;
        }
    }
    __syncthreads();

    const int tl = tid >> 5, to = tid & 31;
    float acc[4][2] = {};
    #pragma unroll 8
    for (int kk = 0; kk < 96; kk++) {
        float b0 = Bs[kk * 65 + to];
        float b1 = Bs[kk * 65 + to + 32];
        #pragma unroll
        for (int i = 0; i < 4; i++) {
            float a = As[(tl * 4 + i) * 96 + kk];
            acc[i][0] += a * b0;
            acc[i][1] += a * b1;
        }
    }
    __syncthreads();
    #pragma unroll
    for (int i = 0; i < 4; i++) {
        Csh[to * 33 + tl * 4 + i] = acc[i][0];
        Csh[(to + 32) * 33 + tl * 4 + i] = acc[i][1];
    }
    __syncthreads();

    for (int e = tid; e < 2048; e += 256) {
        int ol = e >> 5, l = e & 31;
        int o = o0 + ol;
        if (o < DI) g_xc[o * L + l0 + l] = Csh[ol * 33 + l];
    }
    for (int e = tid; e < 2048; e += 256) {
        int l = e >> 6, ol = e & 63;
        int o = o0 + ol;
        if (o >= DI) {
            float v = Csh[ol * 33 + l];
            g_z[(l0 + l) * DI + (o - DI)] = siluf(v);
        }
    }
}

// ---------------- K2: depthwise 3x3 conv + silu + transpose (fused) -------
__global__ void k_conv(const float* __restrict__ cw, const float* __restrict__ cb) {
    __shared__ float sin_[HW * 57];
    __shared__ float sout[HW * 57];
    const int d = blockIdx.x;
    const int tid = threadIdx.x;
    float wgt[9];
    #pragma unroll
    for (int i = 0; i < 9; i++) wgt[i] = cw[d * 9 + i];
    const float bias = cb[d];
    const float* __restrict__ src = g_xc + d * L;
    for (int e = tid; e < L; e += 256)
        sin_[(e / HW) * 57 + (e % HW)] = src[e];
    __syncthreads();

    float* __restrict__ dst = g_xconv + d * L;
    for (int e = tid; e < L; e += 256) {
        int h = e / HW, w = e % HW;
        float acc = bias;
        #pragma unroll
        for (int i = 0; i < 3; i++) {
            int hh = h + i - 1;
            if (hh < 0 || hh >= HW) continue;
            #pragma unroll
            for (int j = 0; j < 3; j++) {
                int ww = w + j - 1;
                if (ww < 0 || ww >= HW) continue;
                acc += sin_[hh * 57 + ww] * wgt[i * 3 + j];
            }
        }
        float v = siluf(acc);
        sout[h * 57 + w] = v;
        dst[e] = v;
    }
    __syncthreads();
    float* __restrict__ dstT = g_xt + d * L;
    for (int e = tid; e < L; e += 256)
        dstT[e] = sout[(e % HW) * 57 + e / HW];
}

// ---------------- K3: x_dbl projection GEMM, scatter into scan order -----
// grid (98, 4): 32-px tiles x 4 directions. 256 thr: tx=px, ty=5-row group.
#define XD_KC 96
__global__ void k_xdbl(const float* __restrict__ xpw) {
    __shared__ __align__(16) float ws[40 * XD_KC];    // [row][dd]
    __shared__ __align__(16) float xs[XD_KC * 32];    // [dd][ss]
    const int k = blockIdx.y;
    const int s0 = blockIdx.x * 32;
    const int tid = threadIdx.x;
    const int tx = tid & 31;
    const int ty = tid >> 5;
    const int r0 = ty * 5;

    float acc[5] = {};

    for (int d0 = 0; d0 < DI; d0 += XD_KC) {
        __syncthreads();
        for (int e4 = tid; e4 < 40 * 24; e4 += 256) {
            int row = e4 / 24, c4 = e4 % 24;
            float4 v = (row < 38)
                ? *(const float4*)&xpw[(k * 38 + row) * DI + d0 + c4 * 4]
                : make_float4(0.f, 0.f, 0.f, 0.f);
            *(float4*)&ws[row * XD_KC + c4 * 4] = v;
        }
        #pragma unroll
        for (int e4 = tid; e4 < XD_KC * 8; e4 += 256) {
            int dd = e4 >> 3, s4 = e4 & 7;
            *(float4*)&xs[dd * 32 + s4 * 4] =
                *(const float4*)&g_xconv[(d0 + dd) * L + s0 + s4 * 4];
        }
        __syncthreads();
        #pragma unroll 8
        for (int dd = 0; dd < XD_KC; dd++) {
            float xv = xs[dd * 32 + tx];
            #pragma unroll
            for (int j = 0; j < 5; j++)
                acc[j] = fmaf(ws[(r0 + j) * XD_KC + dd], xv, acc[j]);
        }
    }

    #pragma unroll
    for (int j = 0; j < 5; j++) {
        int r = r0 + j;
        if (r >= 38) break;
        int s = s0 + tx;
        int hs = s / HW, wsp = s % HW;
        int tpos = wsp * HW + hs;
        int lp = (k == 0) ? s : (k == 1) ? tpos : (k == 2) ? (L - 1 - s) : (L - 1 - tpos);
        float v = acc[j];
        if (r < RR) {
            g_dts[(k * RR + r) * L + lp] = v;
        } else {
            int cc = lp / CL, ii = lp - cc * CL;
            int pos = k * L * NS + (ii * NCH + cc) * NS;
            if (r < RR + NS) g_Bs[pos + (r - RR)] = v;
            else             g_Cs[pos + (r - RR - NS)] = v;
        }
    }
}

// ---------------- K4: fused scan -------------------------------------------
// One block per kd. 256 threads = 64 groups x 4 lanes, chunk = 49 steps.
// fp path (uniform A): sdax holds (dA, delta*x); non-fp: (delta, x).
// sx2 holds x for the epilogue D*x term. stile: warp aggregates + transpose.
template<int K>
__device__ __forceinline__ void scan_body(
    int kd, int d,
    const float* __restrict__ alogs, const float* __restrict__ ds,
    const float* __restrict__ dtw, const float* __restrict__ dtb,
    float2* __restrict__ sdax, float* __restrict__ sx2, float* __restrict__ stile)
{
    const int tid = threadIdx.x;

    // fp detection (block-uniform)
    float4 q0 = *(const float4*)&alogs[kd * NS];
    float4 q1 = *(const float4*)&alogs[kd * NS + 4];
    float4 q2 = *(const float4*)&alogs[kd * NS + 8];
    float4 q3 = *(const float4*)&alogs[kd * NS + 12];
    const bool fp =
        q0.x == q0.y && q0.x == q0.z && q0.x == q0.w &&
        q0.x == q1.x && q0.x == q1.y && q0.x == q1.z && q0.x == q1.w &&
        q0.x == q2.x && q0.x == q2.y && q0.x == q2.z && q0.x == q2.w &&
        q0.x == q3.x && q0.x == q3.y && q0.x == q3.z && q0.x == q3.w;
    const float a2s = -__expf(q0.x) * LOG2E;

    // ---- phase 0: stage (dA|delta, dxv|x) + x ----
    float wr[6];
    #pragma unroll
    for (int r = 0; r < 6; r++) wr[r] = dtw[kd * 6 + r];
    const float b = dtb[kd];
    const float* __restrict__ dbase = g_dts + K * RR * L;
    const float* __restrict__ xsrc = ((K & 1) ? g_xt : g_xconv) + d * L;
    for (int e = tid; e < L; e += 256) {
        float a = b;
        #pragma unroll
        for (int r = 0; r < 6; r++) a = fmaf(dbase[r * L + e], wr[r], a);
        float delta = softplusf(a);
        float xv = (K < 2) ? xsrc[e] : xsrc[L - 1 - e];
        sx2[e] = xv;
        float2 o;
        if (fp) { o.x = ex2f(delta * a2s); o.y = delta * xv; }
        else    { o.x = delta;             o.y = xv; }
        sdax[e] = o;
    }
    __syncthreads();

    // ---- per-lane constants ----
    const int g = tid >> 2, n4 = tid & 3;
    const int lane = tid & 31;
    const int wrp = tid >> 5;
    float4 al = *(const float4*)&alogs[kd * NS + n4 * 4];
    const float a20 = -__expf(al.x) * LOG2E;
    const float a21 = -__expf(al.y) * LOG2E;
    const float a22 = -__expf(al.z) * LOG2E;
    const float a23 = -__expf(al.w) * LOG2E;
    const float* __restrict__ bbase = g_Bs + K * L * NS + n4 * 4;
    const int l0 = g * CL;

    // ---- phase A ----
    float4 P, H;
    {
        float h0 = 0.f, h1 = 0.f, h2 = 0.f, h3 = 0.f;
        if (fp) {
            float Pf = 1.f;
            int l = l0, m = g * NS;
            #pragma unroll 7
            for (int i = 0; i < CL; i++, l++, m += NCH * NS) {
                float2 dx = sdax[l];
                float4 Bv = *(const float4*)&bbase[m];
                h0 = fmaf(dx.x, h0, dx.y * Bv.x);
                h1 = fmaf(dx.x, h1, dx.y * Bv.y);
                h2 = fmaf(dx.x, h2, dx.y * Bv.z);
                h3 = fmaf(dx.x, h3, dx.y * Bv.w);
                Pf *= dx.x;
            }
            P.x = Pf; P.y = Pf; P.z = Pf; P.w = Pf;
        } else {
            float sd = 0.f;
            int l = l0, m = g * NS;
            #pragma unroll 7
            for (int i = 0; i < CL; i++, l++, m += NCH * NS) {
                float2 dx = sdax[l];
                float4 Bv = *(const float4*)&bbase[m];
                float dxv = dx.x * dx.y;
                h0 = fmaf(ex2f(dx.x * a20), h0, dxv * Bv.x);
                h1 = fmaf(ex2f(dx.x * a21), h1, dxv * Bv.y);
                h2 = fmaf(ex2f(dx.x * a22), h2, dxv * Bv.z);
                h3 = fmaf(ex2f(dx.x * a23), h3, dxv * Bv.w);
                sd += dx.x;
            }
            P.x = ex2f(a20 * sd); P.y = ex2f(a21 * sd);
            P.z = ex2f(a22 * sd); P.w = ex2f(a23 * sd);
        }
        H.x = h0; H.y = h1; H.z = h2; H.w = h3;
    }

    // ---- chunk scan: intra-warp shuffle KS + warp-aggregate fold ----
    const unsigned FULL = 0xffffffffu;
    #pragma unroll
    for (int off = 4; off <= 16; off <<= 1) {
        float4 Pp, Hp;
        Pp.x = __shfl_up_sync(FULL, P.x, off);
        Pp.y = __shfl_up_sync(FULL, P.y, off);
        Pp.z = __shfl_up_sync(FULL, P.z, off);
        Pp.w = __shfl_up_sync(FULL, P.w, off);
        Hp.x = __shfl_up_sync(FULL, H.x, off);
        Hp.y = __shfl_up_sync(FULL, H.y, off);
        Hp.z = __shfl_up_sync(FULL, H.z, off);
        Hp.w = __shfl_up_sync(FULL, H.w, off);
        if (lane >= off) {
            H.x = fmaf(P.x, Hp.x, H.x); P.x *= Pp.x;
            H.y = fmaf(P.y, Hp.y, H.y); P.y *= Pp.y;
            H.z = fmaf(P.z, Hp.z, H.z); P.z *= Pp.z;
            H.w = fmaf(P.w, Hp.w, H.w); P.w *= Pp.w;
        }
    }
    // exclusive within warp
    float4 Pe, He;
    Pe.x = __shfl_up_sync(FULL, P.x, 4);
    Pe.y = __shfl_up_sync(FULL, P.y, 4);
    Pe.z = __shfl_up_sync(FULL, P.z, 4);
    Pe.w = __shfl_up_sync(FULL, P.w, 4);
    He.x = __shfl_up_sync(FULL, H.x, 4);
    He.y = __shfl_up_sync(FULL, H.y, 4);
    He.z = __shfl_up_sync(FULL, H.z, 4);
    He.w = __shfl_up_sync(FULL, H.w, 4);
    if (lane < 4) { Pe.x = Pe.y = Pe.z = Pe.w = 1.f; He.x = He.y = He.z = He.w = 0.f; }
    // warp totals (g'=7 lanes 28..31, n4 = lane-28)
    if (lane >= 28) {
        int idx = (wrp * 4 + (lane - 28)) * 8;
        *(float4*)&stile[idx] = P;
        *(float4*)&stile[idx + 4] = H;
    }
    __syncthreads();
    float4 Hc = {0.f, 0.f, 0.f, 0.f};
    for (int w2 = 0; w2 < wrp; w2++) {
        float4 Pw = *(const float4*)&stile[(w2 * 4 + n4) * 8];
        float4 Hw = *(const float4*)&stile[(w2 * 4 + n4) * 8 + 4];
        Hc.x = fmaf(Pw.x, Hc.x, Hw.x);
        Hc.y = fmaf(Pw.y, Hc.y, Hw.y);
        Hc.z = fmaf(Pw.z, Hc.z, Hw.z);
        Hc.w = fmaf(Pw.w, Hc.w, Hw.w);
    }
    float4 Hin;
    Hin.x = fmaf(Pe.x, Hc.x, He.x);
    Hin.y = fmaf(Pe.y, Hc.y, He.y);
    Hin.z = fmaf(Pe.z, Hc.z, He.z);
    Hin.w = fmaf(Pe.w, Hc.w, He.w);
    __syncthreads();   // stile reads done before epilogue reuse

    // ---- phase C: replay chunk, write v into sdax[l].x ----
    const float* __restrict__ cbase = g_Cs + K * L * NS + n4 * 4;
    {
        float h0 = Hin.x, h1 = Hin.y, h2 = Hin.z, h3 = Hin.w;
        if (fp) {
            int l = l0, m = g * NS;
            #pragma unroll 7
            for (int i = 0; i < CL; i++, l++, m += NCH * NS) {
                float2 dx = sdax[l];
                float4 Bv = *(const float4*)&bbase[m];
                float4 Cv = *(const float4*)&cbase[m];
                h0 = fmaf(dx.x, h0, dx.y * Bv.x);
                h1 = fmaf(dx.x, h1, dx.y * Bv.y);
                h2 = fmaf(dx.x, h2, dx.y * Bv.z);
                h3 = fmaf(dx.x, h3, dx.y * Bv.w);
                float v = h0 * Cv.x + h1 * Cv.y + h2 * Cv.z + h3 * Cv.w;
                v += __shfl_xor_sync(FULL, v, 1);
                v += __shfl_xor_sync(FULL, v, 2);
                if (n4 == 0) sdax[l].x = v;   // same-warp read precedes write
            }
        } else {
            int l = l0, m = g * NS;
            #pragma unroll 7
            for (int i = 0; i < CL; i++, l++, m += NCH * NS) {
                float2 dx = sdax[l];
                float4 Bv = *(const float4*)&bbase[m];
                float4 Cv = *(const float4*)&cbase[m];
                float dxv = dx.x * dx.y;
                h0 = fmaf(ex2f(dx.x * a20), h0, dxv * Bv.x);
                h1 = fmaf(ex2f(dx.x * a21), h1, dxv * Bv.y);
                h2 = fmaf(ex2f(dx.x * a22), h2, dxv * Bv.z);
                h3 = fmaf(ex2f(dx.x * a23), h3, dxv * Bv.w);
                float v = h0 * Cv.x + h1 * Cv.y + h2 * Cv.z + h3 * Cv.w;
                v += __shfl_xor_sync(FULL, v, 1);
                v += __shfl_xor_sync(FULL, v, 2);
                if (n4 == 0) sdax[l].x = v;
            }
        }
    }
    __syncthreads();

    // ---- epilogue: y = v + Dv*x, coalesced at spatial index ----
    const float Dv = ds[kd];
    float* __restrict__ yptr = g_y4 + kd * L;
    if (K == 0) {
        for (int e = tid; e < L; e += 256)
            yptr[e] = fmaf(Dv, sx2[e], sdax[e].x);
    } else if (K == 2) {
        for (int e = tid; e < L; e += 256)
            yptr[e] = fmaf(Dv, sx2[L - 1 - e], sdax[L - 1 - e].x);
    } else {
        for (int h0t = 0; h0t < HW; h0t += 28) {
            __syncthreads();
            for (int e2 = tid; e2 < HW * 28; e2 += 256) {
                int w = e2 / 28, hh = e2 % 28;
                int l = w * HW + h0t + hh;
                int li = (K == 1) ? l : (L - 1 - l);
                stile[hh * 57 + w] = fmaf(Dv, sx2[li], sdax[li].x);
            }
            __syncthreads();
            for (int e2 = tid; e2 < HW * 28; e2 += 256) {
                int w = e2 % HW, hh = e2 / HW;
                yptr[(h0t + hh) * HW + w] = stile[hh * 57 + w];
            }
        }
    }
}

__global__ void __launch_bounds__(256, 5) k_scan(
        const float* __restrict__ alogs, const float* __restrict__ ds,
        const float* __restrict__ dtw, const float* __restrict__ dtb) {
    __shared__ __align__(16) float2 sdax[L];
    __shared__ float sx2[L];
    __shared__ __align__(16) float stile[1600];
    const int kd = blockIdx.x;
    const int k = kd / DI, d = kd % DI;
    switch (k) {
        case 0: scan_body<0>(kd, d, alogs, ds, dtw, dtb, sdax, sx2, stile); break;
        case 1: scan_body<1>(kd, d, alogs, ds, dtw, dtb, sdax, sx2, stile); break;
        case 2: scan_body<2>(kd, d, alogs, ds, dtw, dtb, sdax, sx2, stile); break;
        default: scan_body<3>(kd, d, alogs, ds, dtw, dtb, sdax, sx2, stile); break;
    }
}

// ---------------- K5: merge 4 dirs + LayerNorm + z-gate + out_proj --------
__global__ void k_merge_out(const float* __restrict__ lnw, const float* __restrict__ lnb,
                            const float* __restrict__ ow, float* __restrict__ out) {
    __shared__ float yt[DI * 33];
    __shared__ float red1[256], red2[256];
    __shared__ float mu_s[32], rs_s[32];
    const int s0 = blockIdx.x * 32;
    const int tid = threadIdx.x;

    for (int e = tid; e < DI * 32; e += 256) {
        int d = e >> 5, ls = e & 31;
        int s = s0 + ls;
        float v = g_y4[d * L + s] + g_y4[(DI + d) * L + s] +
                  g_y4[(2 * DI + d) * L + s] + g_y4[(3 * DI + d) * L + s];
        yt[d * 33 + ls] = v;
    }
    __syncthreads();
    {
        int j = tid >> 5, ls = tid & 31;
        float s1 = 0.f, s2 = 0.f;
        for (int d = j; d < DI; d += 8) {
            float v = yt[d * 33 + ls];
            s1 += v; s2 += v * v;
        }
        red1[tid] = s1; red2[tid] = s2;
    }
    __syncthreads();
    if (tid < 32) {
        float s1 = 0.f, s2 = 0.f;
        #pragma unroll
        for (int j = 0; j < 8; j++) { s1 += red1[j * 32 + tid]; s2 += red2[j * 32 + tid]; }
        float mu = s1 / DI;
        float var = s2 / DI - mu * mu;
        mu_s[tid] = mu;
        rs_s[tid] = rsqrtf(var + 1e-5f);
    }
    __syncthreads();
    for (int e = tid; e < DI * 32; e += 256) {
        int ls = e / DI, d = e % DI;
        float v = yt[d * 33 + ls];
        v = (v - mu_s[ls]) * rs_s[ls] * lnw[d] + lnb[d];
        v *= g_z[(s0 + ls) * DI + d];
        yt[d * 33 + ls] = v;
    }
    __syncthreads();
    {
        int ls = tid & 31, og = tid >> 5;
        float acc[12] = {};
        for (int d = 0; d < DI; d++) {
            float yv = yt[d * 33 + ls];
            #pragma unroll
            for (int j = 0; j < 12; j++) acc[j] += yv * __ldg(&ow[(og + 8 * j) * DI + d]);
        }
        #pragma unroll
        for (int j = 0; j < 12; j++) out[(s0 + ls) * DM + og + 8 * j] = acc[j];
    }
}

// ---------------- launch ---------------------------------------------------
extern "C" void kernel_launch(void* const* d_in, const int* in_sizes, int n_in,
                              void* d_out, int out_size) {
    const float* x     = (const float*)d_in[0];
    const float* inw   = (const float*)d_in[1];
    const float* cw    = (const float*)d_in[2];
    const float* cb    = (const float*)d_in[3];
    const float* xpw   = (const float*)d_in[4];
    const float* dtw   = (const float*)d_in[5];
    const float* dtb   = (const float*)d_in[6];
    const float* alogs = (const float*)d_in[7];
    const float* ds    = (const float*)d_in[8];
    const float* lnw   = (const float*)d_in[9];
    const float* lnb   = (const float*)d_in[10];
    const float* ow    = (const float*)d_in[11];
    float* out = (float*)d_out;

    k_inproj<<<dim3(98, 6), 256>>>(x, inw);
    k_conv<<<192, 256>>>(cw, cb);
    k_xdbl<<<dim3(98, 4), 256>>>(xpw);
    k_scan<<<768, 256>>>(alogs, ds, dtw, dtb);
    k_merge_out<<<98, 256>>>(lnw, lnb, ow, out);
}

// round 17
// speedup vs baseline: 1.0460x; 1.0460x over previous
#include <cuda_runtime.h>
#include <math.h>

#define L    3136
#define HW   56
#define DM   96
#define DI   192
#define NS   16
#define KDIR 4
#define RR   6
#define NCH  64
#define CL   49

// ---------------- scratch (device globals; no allocation) ----------------
__device__ float g_xc[DI * L];           // conv input, channel-major [d][s]
__device__ float g_z[L * DI];            // gate, pixel-major [s][d]
__device__ float g_xconv[DI * L];        // conv output, channel-major [d][s]
__device__ float g_xt[DI * L];           // transposed
__device__ float g_dts[KDIR * RR * L];   // low-rank dt, scan order [k*6+r][l]
// B/C in CHUNK-INTERLEAVED scan order: index (i*64+c)*16+n where l = c*49+i
__device__ float g_Bs[KDIR * L * NS];
__device__ float g_Cs[KDIR * L * NS];
__device__ float g_y4[KDIR * DI * L];    // per-direction y at SPATIAL index

__device__ __forceinline__ float siluf(float x) { return x / (1.f + __expf(-x)); }
__device__ __forceinline__ float softplusf(float x) {
    return x > 20.f ? x : __logf(1.f + __expf(x));
}
__device__ __forceinline__ float ex2f(float x) {
    float r;
    asm("ex2.approx.f32 %0, %1;" : "=f"(r) : "f"(x));
    return r;
}
#define LOG2E 1.4426950408889634f

// ---------------- K1: in_proj GEMM (L x 96) @ (96 x 384), split xc/z ------
__global__ void k_inproj(const float* __restrict__ x, const float* __restrict__ w) {
    __shared__ __align__(16) float As[32 * 96];
    __shared__ __align__(16) float Bs[96 * 65];
    __shared__ float Csh[64 * 33];
    const int l0 = blockIdx.x * 32;
    const int o0 = blockIdx.y * 64;
    const int tid = threadIdx.x;

    {
        const float4* x4 = (const float4*)x;
        float4* As4 = (float4*)As;
        for (int e4 = tid; e4 < 32 * 24; e4 += 256)
            As4[e4] = x4[l0 * 24 + e4];
        for (int e4 = tid; e4 < 64 * 24; e4 += 256) {
            int o = e4 / 24, c4 = e4 % 24;
            float4 wv = *(const float4*)&w[(o0 + o) * 96 + c4 * 4];
            int c = c4 * 4;
            Bs[(c + 0) * 65 + o] = wv.x;
            Bs[(c + 1) * 65 + o] = wv.y;
            Bs[(c + 2) * 65 + o] = wv.z;
            Bs[(c + 3) * 65 + o] = wv.w;
        }
    }
    __syncthreads();

    const int tl = tid >> 5, to = tid & 31;
    float acc[4][2] = {};
    #pragma unroll 8
    for (int kk = 0; kk < 96; kk++) {
        float b0 = Bs[kk * 65 + to];
        float b1 = Bs[kk * 65 + to + 32];
        #pragma unroll
        for (int i = 0; i < 4; i++) {
            float a = As[(tl * 4 + i) * 96 + kk];
            acc[i][0] += a * b0;
            acc[i][1] += a * b1;
        }
    }
    __syncthreads();
    #pragma unroll
    for (int i = 0; i < 4; i++) {
        Csh[to * 33 + tl * 4 + i] = acc[i][0];
        Csh[(to + 32) * 33 + tl * 4 + i] = acc[i][1];
    }
    __syncthreads();

    for (int e = tid; e < 2048; e += 256) {
        int ol = e >> 5, l = e & 31;
        int o = o0 + ol;
        if (o < DI) g_xc[o * L + l0 + l] = Csh[ol * 33 + l];
    }
    for (int e = tid; e < 2048; e += 256) {
        int l = e >> 6, ol = e & 63;
        int o = o0 + ol;
        if (o >= DI) {
            float v = Csh[ol * 33 + l];
            g_z[(l0 + l) * DI + (o - DI)] = siluf(v);
        }
    }
}

// ---------------- K2: depthwise 3x3 conv + silu + transpose (fused) -------
__global__ void k_conv(const float* __restrict__ cw, const float* __restrict__ cb) {
    __shared__ float sin_[HW * 57];
    __shared__ float sout[HW * 57];
    const int d = blockIdx.x;
    const int tid = threadIdx.x;
    float wgt[9];
    #pragma unroll
    for (int i = 0; i < 9; i++) wgt[i] = cw[d * 9 + i];
    const float bias = cb[d];
    const float* __restrict__ src = g_xc + d * L;
    for (int e = tid; e < L; e += 256)
        sin_[(e / HW) * 57 + (e % HW)] = src[e];
    __syncthreads();

    float* __restrict__ dst = g_xconv + d * L;
    for (int e = tid; e < L; e += 256) {
        int h = e / HW, w = e % HW;
        float acc = bias;
        #pragma unroll
        for (int i = 0; i < 3; i++) {
            int hh = h + i - 1;
            if (hh < 0 || hh >= HW) continue;
            #pragma unroll
            for (int j = 0; j < 3; j++) {
                int ww = w + j - 1;
                if (ww < 0 || ww >= HW) continue;
                acc += sin_[hh * 57 + ww] * wgt[i * 3 + j];
            }
        }
        float v = siluf(acc);
        sout[h * 57 + w] = v;
        dst[e] = v;
    }
    __syncthreads();
    float* __restrict__ dstT = g_xt + d * L;
    for (int e = tid; e < L; e += 256)
        dstT[e] = sout[(e % HW) * 57 + e / HW];
}

// ---------------- K3: x_dbl projection GEMM, scatter into scan order -----
#define XD_KC 96
__global__ void k_xdbl(const float* __restrict__ xpw) {
    __shared__ __align__(16) float ws[40 * XD_KC];    // [row][dd]
    __shared__ __align__(16) float xs[XD_KC * 32];    // [dd][ss]
    const int k = blockIdx.y;
    const int s0 = blockIdx.x * 32;
    const int tid = threadIdx.x;
    const int tx = tid & 31;
    const int ty = tid >> 5;
    const int r0 = ty * 5;

    float acc[5] = {};

    for (int d0 = 0; d0 < DI; d0 += XD_KC) {
        __syncthreads();
        for (int e4 = tid; e4 < 40 * 24; e4 += 256) {
            int row = e4 / 24, c4 = e4 % 24;
            float4 v = (row < 38)
                ? *(const float4*)&xpw[(k * 38 + row) * DI + d0 + c4 * 4]
                : make_float4(0.f, 0.f, 0.f, 0.f);
            *(float4*)&ws[row * XD_KC + c4 * 4] = v;
        }
        #pragma unroll
        for (int e4 = tid; e4 < XD_KC * 8; e4 += 256) {
            int dd = e4 >> 3, s4 = e4 & 7;
            *(float4*)&xs[dd * 32 + s4 * 4] =
                *(const float4*)&g_xconv[(d0 + dd) * L + s0 + s4 * 4];
        }
        __syncthreads();
        #pragma unroll 8
        for (int dd = 0; dd < XD_KC; dd++) {
            float xv = xs[dd * 32 + tx];
            #pragma unroll
            for (int j = 0; j < 5; j++)
                acc[j] = fmaf(ws[(r0 + j) * XD_KC + dd], xv, acc[j]);
        }
    }

    #pragma unroll
    for (int j = 0; j < 5; j++) {
        int r = r0 + j;
        if (r >= 38) break;
        int s = s0 + tx;
        int hs = s / HW, wsp = s % HW;
        int tpos = wsp * HW + hs;
        int lp = (k == 0) ? s : (k == 1) ? tpos : (k == 2) ? (L - 1 - s) : (L - 1 - tpos);
        float v = acc[j];
        if (r < RR) {
            g_dts[(k * RR + r) * L + lp] = v;
        } else {
            int cc = lp / CL, ii = lp - cc * CL;
            int pos = k * L * NS + (ii * NCH + cc) * NS;
            if (r < RR + NS) g_Bs[pos + (r - RR)] = v;
            else             g_Cs[pos + (r - RR - NS)] = v;
        }
    }
}

// ---------------- K4: fused scan (R15 configuration) -----------------------
// One block per kd. 256 threads = 64 groups x 4 lanes, chunk = 49 steps.
template<int K>
__device__ __forceinline__ void scan_body(
    int kd, int d,
    const float* __restrict__ alogs, const float* __restrict__ ds,
    const float* __restrict__ dtw, const float* __restrict__ dtb,
    float2* __restrict__ sdx, float* __restrict__ sps)
{
    const int tid = threadIdx.x;
    float* __restrict__ sP = sps;          // [0..1023]
    float* __restrict__ sH = sps + 1024;   // [1024..2047]

    // ---- phase 0: sdx[e] = (delta, x) in scan order (x from xconv/xt) ----
    float wr[6];
    #pragma unroll
    for (int r = 0; r < 6; r++) wr[r] = dtw[kd * 6 + r];
    const float b = dtb[kd];
    const float* __restrict__ dbase = g_dts + K * RR * L;
    const float* __restrict__ xsrc = ((K & 1) ? g_xt : g_xconv) + d * L;
    for (int e = tid; e < L; e += 256) {
        float a = b;
        #pragma unroll
        for (int r = 0; r < 6; r++) a = fmaf(dbase[r * L + e], wr[r], a);
        float xv = (K < 2) ? xsrc[e] : xsrc[L - 1 - e];
        float2 o; o.x = softplusf(a); o.y = xv;
        sdx[e] = o;
    }
    __syncthreads();

    // ---- setup per-lane state constants + fast-path detection ----
    const int g = tid >> 2, n4 = tid & 3;
    float4 al = *(const float4*)&alogs[kd * NS + n4 * 4];
    const float a20 = -__expf(al.x) * LOG2E;
    const float a21 = -__expf(al.y) * LOG2E;
    const float a22 = -__expf(al.z) * LOG2E;
    const float a23 = -__expf(al.w) * LOG2E;
    bool fp = (al.x == al.y) && (al.x == al.z) && (al.x == al.w) &&
              (al.x == __shfl_sync(0xffffffffu, al.x, 0));
    fp = __all_sync(0xffffffffu, fp);

    const float* __restrict__ bbase = g_Bs + K * L * NS + n4 * 4;
    const int l0 = g * CL;

    // ---- phase A: per-chunk scan ----
    float h0 = 0.f, h1 = 0.f, h2 = 0.f, h3 = 0.f, sd = 0.f;
    if (fp) {
        int l = l0, m = g * NS;
        #pragma unroll 7
        for (int i = 0; i < CL; i++, l++, m += NCH * NS) {
            float2 dx = sdx[l];
            float4 Bv = *(const float4*)&bbase[m];
            float dxv = dx.x * dx.y;
            float dA = ex2f(dx.x * a20);
            h0 = fmaf(dA, h0, dxv * Bv.x);
            h1 = fmaf(dA, h1, dxv * Bv.y);
            h2 = fmaf(dA, h2, dxv * Bv.z);
            h3 = fmaf(dA, h3, dxv * Bv.w);
            sd += dx.x;
        }
    } else {
        int l = l0, m = g * NS;
        #pragma unroll 7
        for (int i = 0; i < CL; i++, l++, m += NCH * NS) {
            float2 dx = sdx[l];
            float4 Bv = *(const float4*)&bbase[m];
            float dxv = dx.x * dx.y;
            h0 = fmaf(ex2f(dx.x * a20), h0, dxv * Bv.x);
            h1 = fmaf(ex2f(dx.x * a21), h1, dxv * Bv.y);
            h2 = fmaf(ex2f(dx.x * a22), h2, dxv * Bv.z);
            h3 = fmaf(ex2f(dx.x * a23), h3, dxv * Bv.w);
            sd += dx.x;
        }
    }
    float4 P, H;
    if (fp) { P.x = ex2f(a20 * sd); P.y = P.x; P.z = P.x; P.w = P.x; }
    else {
        P.x = ex2f(a20 * sd); P.y = ex2f(a21 * sd);
        P.z = ex2f(a22 * sd); P.w = ex2f(a23 * sd);
    }
    H.x = h0; H.y = h1; H.z = h2; H.w = h3;
    *(float4*)&sP[tid * 4] = P;
    *(float4*)&sH[tid * 4] = H;
    __syncthreads();

    // ---- phase B: Kogge-Stone inclusive scan over 64 chunks ----
    #pragma unroll
    for (int off = 1; off < NCH; off <<= 1) {
        float4 Pp, Hp;
        const bool valid = (g >= off);
        if (valid) {
            Pp = *(const float4*)&sP[(tid - off * 4) * 4];
            Hp = *(const float4*)&sH[(tid - off * 4) * 4];
        }
        __syncthreads();
        if (valid) {
            H.x = fmaf(P.x, Hp.x, H.x); P.x *= Pp.x;
            H.y = fmaf(P.y, Hp.y, H.y); P.y *= Pp.y;
            H.z = fmaf(P.z, Hp.z, H.z); P.z *= Pp.z;
            H.w = fmaf(P.w, Hp.w, H.w); P.w *= Pp.w;
            *(float4*)&sP[tid * 4] = P;
            *(float4*)&sH[tid * 4] = H;
        }
        __syncthreads();
    }

    float4 Hin = {0.f, 0.f, 0.f, 0.f};
    if (g > 0) Hin = *(const float4*)&sH[(tid - 4) * 4];
    __syncthreads();   // Hin reads done before sps is reused by epilogue

    // ---- phase C: replay chunk with h_in, write y into sdx[l].x ----
    const float Dv = ds[kd];
    const float* __restrict__ cbase = g_Cs + K * L * NS + n4 * 4;
    h0 = Hin.x; h1 = Hin.y; h2 = Hin.z; h3 = Hin.w;

    if (fp) {
        int l = l0, m = g * NS;
        #pragma unroll 7
        for (int i = 0; i < CL; i++, l++, m += NCH * NS) {
            float2 dx = sdx[l];
            float4 Bv = *(const float4*)&bbase[m];
            float4 Cv = *(const float4*)&cbase[m];
            float dxv = dx.x * dx.y;
            float dA = ex2f(dx.x * a20);
            h0 = fmaf(dA, h0, dxv * Bv.x);
            h1 = fmaf(dA, h1, dxv * Bv.y);
            h2 = fmaf(dA, h2, dxv * Bv.z);
            h3 = fmaf(dA, h3, dxv * Bv.w);
            float v = h0 * Cv.x + h1 * Cv.y + h2 * Cv.z + h3 * Cv.w;
            v += __shfl_xor_sync(0xffffffffu, v, 1);
            v += __shfl_xor_sync(0xffffffffu, v, 2);
            if (n4 == 0) sdx[l].x = fmaf(Dv, dx.y, v);  // same-warp read-then-write
        }
    } else {
        int l = l0, m = g * NS;
        #pragma unroll 7
        for (int i = 0; i < CL; i++, l++, m += NCH * NS) {
            float2 dx = sdx[l];
            float4 Bv = *(const float4*)&bbase[m];
            float4 Cv = *(const float4*)&cbase[m];
            float dxv = dx.x * dx.y;
            h0 = fmaf(ex2f(dx.x * a20), h0, dxv * Bv.x);
            h1 = fmaf(ex2f(dx.x * a21), h1, dxv * Bv.y);
            h2 = fmaf(ex2f(dx.x * a22), h2, dxv * Bv.z);
            h3 = fmaf(ex2f(dx.x * a23), h3, dxv * Bv.w);
            float v = h0 * Cv.x + h1 * Cv.y + h2 * Cv.z + h3 * Cv.w;
            v += __shfl_xor_sync(0xffffffffu, v, 1);
            v += __shfl_xor_sync(0xffffffffu, v, 2);
            if (n4 == 0) sdx[l].x = fmaf(Dv, dx.y, v);
        }
    }
    __syncthreads();

    // ---- epilogue: write y coalesced at spatial index ----
    float* __restrict__ yptr = g_y4 + kd * L;
    if (K == 0) {
        for (int e = tid; e < L; e += 256) yptr[e] = sdx[e].x;
    } else if (K == 2) {
        for (int e = tid; e < L; e += 256) yptr[e] = sdx[L - 1 - e].x;
    } else {
        for (int h0t = 0; h0t < HW; h0t += 28) {
            __syncthreads();
            for (int e2 = tid; e2 < HW * 28; e2 += 256) {
                int w = e2 / 28, hh = e2 % 28;
                int l = w * HW + h0t + hh;
                int li = (K == 1) ? l : (L - 1 - l);
                sps[hh * 57 + w] = sdx[li].x;
            }
            __syncthreads();
            for (int e2 = tid; e2 < HW * 28; e2 += 256) {
                int w = e2 % HW, hh = e2 / HW;
                yptr[(h0t + hh) * HW + w] = sps[hh * 57 + w];
            }
        }
    }
}

__global__ void __launch_bounds__(256, 6) k_scan(
        const float* __restrict__ alogs, const float* __restrict__ ds,
        const float* __restrict__ dtw, const float* __restrict__ dtb) {
    __shared__ float2 sdx[L];
    __shared__ float sps[2048];
    const int kd = blockIdx.x;
    const int k = kd / DI, d = kd % DI;
    switch (k) {
        case 0: scan_body<0>(kd, d, alogs, ds, dtw, dtb, sdx, sps); break;
        case 1: scan_body<1>(kd, d, alogs, ds, dtw, dtb, sdx, sps); break;
        case 2: scan_body<2>(kd, d, alogs, ds, dtw, dtb, sdx, sps); break;
        default: scan_body<3>(kd, d, alogs, ds, dtw, dtb, sdx, sps); break;
    }
}

// ---------------- K5: merge 4 dirs + LayerNorm + z-gate + out_proj --------
__global__ void k_merge_out(const float* __restrict__ lnw, const float* __restrict__ lnb,
                            const float* __restrict__ ow, float* __restrict__ out) {
    __shared__ float yt[DI * 33];
    __shared__ float red1[256], red2[256];
    __shared__ float mu_s[32], rs_s[32];
    const int s0 = blockIdx.x * 32;
    const int tid = threadIdx.x;

    for (int e = tid; e < DI * 32; e += 256) {
        int d = e >> 5, ls = e & 31;
        int s = s0 + ls;
        float v = g_y4[d * L + s] + g_y4[(DI + d) * L + s] +
                  g_y4[(2 * DI + d) * L + s] + g_y4[(3 * DI + d) * L + s];
        yt[d * 33 + ls] = v;
    }
    __syncthreads();
    {
        int j = tid >> 5, ls = tid & 31;
        float s1 = 0.f, s2 = 0.f;
        for (int d = j; d < DI; d += 8) {
            float v = yt[d * 33 + ls];
            s1 += v; s2 += v * v;
        }
        red1[tid] = s1; red2[tid] = s2;
    }
    __syncthreads();
    if (tid < 32) {
        float s1 = 0.f, s2 = 0.f;
        #pragma unroll
        for (int j = 0; j < 8; j++) { s1 += red1[j * 32 + tid]; s2 += red2[j * 32 + tid]; }
        float mu = s1 / DI;
        float var = s2 / DI - mu * mu;
        mu_s[tid] = mu;
        rs_s[tid] = rsqrtf(var + 1e-5f);
    }
    __syncthreads();
    for (int e = tid; e < DI * 32; e += 256) {
        int ls = e / DI, d = e % DI;
        float v = yt[d * 33 + ls];
        v = (v - mu_s[ls]) * rs_s[ls] * lnw[d] + lnb[d];
        v *= g_z[(s0 + ls) * DI + d];
        yt[d * 33 + ls] = v;
    }
    __syncthreads();
    {
        int ls = tid & 31, og = tid >> 5;
        float acc[12] = {};
        for (int d = 0; d < DI; d++) {
            float yv = yt[d * 33 + ls];
            #pragma unroll
            for (int j = 0; j < 12; j++) acc[j] += yv * __ldg(&ow[(og + 8 * j) * DI + d]);
        }
        #pragma unroll
        for (int j = 0; j < 12; j++) out[(s0 + ls) * DM + og + 8 * j] = acc[j];
    }
}

// ---------------- launch ---------------------------------------------------
extern "C" void kernel_launch(void* const* d_in, const int* in_sizes, int n_in,
                              void* d_out, int out_size) {
    const float* x     = (const float*)d_in[0];
    const float* inw   = (const float*)d_in[1];
    const float* cw    = (const float*)d_in[2];
    const float* cb    = (const float*)d_in[3];
    const float* xpw   = (const float*)d_in[4];
    const float* dtw   = (const float*)d_in[5];
    const float* dtb   = (const float*)d_in[6];
    const float* alogs = (const float*)d_in[7];
    const float* ds    = (const float*)d_in[8];
    const float* lnw   = (const float*)d_in[9];
    const float* lnb   = (const float*)d_in[10];
    const float* ow    = (const float*)d_in[11];
    float* out = (float*)d_out;

    k_inproj<<<dim3(98, 6), 256>>>(x, inw);
    k_conv<<<192, 256>>>(cw, cb);
    k_xdbl<<<dim3(98, 4), 256>>>(xpw);
    k_scan<<<768, 256>>>(alogs, ds, dtw, dtb);
    k_merge_out<<<98, 256>>>(lnw, lnb, ow, out);
}